// round 1
// baseline (speedup 1.0000x reference)
#include <cuda_runtime.h>
#include <cstdint>

// Problem constants (fixed by the reference)
#define NTOK   8192      // B*S = 64*128
#define T_SLOT 16
#define E_DIM  1024      // token embedding width (floats)
#define D_DIM  100       // entity embedding width (floats)
#define OUT_W  (E_DIM + D_DIM)   // 1124

__global__ __launch_bounds__(128, 8)
void fuse_triples_kernel(const int*   __restrict__ inputs,      // [NTOK]
                         const int*   __restrict__ triples,     // [NTOK, T, 3]
                         const int*   __restrict__ flags,       // [NTOK, T]
                         const float* __restrict__ emb,         // [VOCAB, 1024]
                         const float* __restrict__ ent,         // [ENT_VOCAB, 100]
                         float*       __restrict__ out)         // [NTOK, 1124]
{
    const int token = blockIdx.x;
    const int tid   = threadIdx.x;

    // ---- Stage A: decode triple slots into shared memory (threads 0..15) ----
    __shared__ int s_idx[T_SLOT];
    if (tid < T_SLOT) {
        const int f = flags[token * T_SLOT + tid];
        int e = -1;
        if (f == 1) {
            e = triples[(token * T_SLOT + tid) * 3 + 1];   // tail entity
        } else if (f == 2) {
            e = triples[(token * T_SLOT + tid) * 3 + 0];   // head entity
        }
        s_idx[tid] = e;
    }

    // ---- Stage B: token embedding copy, 1024 floats = 256 float4 ----
    const int vrow = inputs[token];
    const float4* __restrict__ src =
        reinterpret_cast<const float4*>(emb + (size_t)vrow * E_DIM);
    // out row base: 1124 floats * 4B = 4496 B, 16B-aligned -> float4 OK
    float4* __restrict__ dst =
        reinterpret_cast<float4*>(out + (size_t)token * OUT_W);

    float4 v0 = src[tid];
    float4 v1 = src[tid + 128];

    __syncthreads();   // s_idx visible

    dst[tid]       = v0;
    dst[tid + 128] = v1;

    // ---- Stage C: entity gather + average (threads 0..24, float4 lanes) ----
    // Each entity row is 100 floats = 400 B = 25 float4, 16B-aligned.
    if (tid < 25) {
        float4 acc = make_float4(0.f, 0.f, 0.f, 0.f);
        int cnt = 0;
        #pragma unroll
        for (int j = 0; j < T_SLOT; ++j) {
            const int e = s_idx[j];
            if (e >= 0) {
                const float4 r = reinterpret_cast<const float4*>(
                                     ent + (size_t)e * D_DIM)[tid];
                acc.x += r.x; acc.y += r.y; acc.z += r.z; acc.w += r.w;
                ++cnt;
            }
        }
        const float inv = 1.0f / (float)(cnt > 0 ? cnt : 1);
        acc.x *= inv; acc.y *= inv; acc.z *= inv; acc.w *= inv;
        reinterpret_cast<float4*>(out + (size_t)token * OUT_W + E_DIM)[tid] = acc;
    }
}

extern "C" void kernel_launch(void* const* d_in, const int* in_sizes, int n_in,
                              void* d_out, int out_size)
{
    const int*   inputs  = (const int*)  d_in[0];   // [B,S] int32
    const int*   triples = (const int*)  d_in[1];   // [B,S,T,3] int32
    const int*   flags   = (const int*)  d_in[2];   // [B,S,T] int32
    const float* emb     = (const float*)d_in[3];   // [VOCAB, 1024] f32
    const float* ent     = (const float*)d_in[4];   // [ENT_VOCAB, 100] f32
    float*       out     = (float*)      d_out;     // [B,S,1124] f32

    fuse_triples_kernel<<<NTOK, 128>>>(inputs, triples, flags, emb, ent, out);
}

// round 2
// speedup vs baseline: 1.2321x; 1.2321x over previous
#include <cuda_runtime.h>
#include <cstdint>

#define NTOK   8192              // B*S
#define T_SLOT 16
#define E_DIM  1024
#define D_DIM  100
#define OUT_W  (E_DIM + D_DIM)   // 1124

__global__ __launch_bounds__(256)
void fuse_triples_warp_kernel(const int*   __restrict__ inputs,   // [NTOK]
                              const int*   __restrict__ triples,  // [NTOK,T,3]
                              const int*   __restrict__ flags,    // [NTOK,T]
                              const float* __restrict__ emb,      // [VOCAB,1024]
                              const float* __restrict__ ent,      // [ENT_VOCAB,100]
                              float*       __restrict__ out)      // [NTOK,1124]
{
    const int gwarp = (blockIdx.x * blockDim.x + threadIdx.x) >> 5;
    const int lane  = threadIdx.x & 31;
    if (gwarp >= NTOK) return;
    const int token = gwarp;

    // ---- decode triple slots, one slot per lane (lanes 0..15) ----
    int e = -1;
    if (lane < T_SLOT) {
        const int f = flags[token * T_SLOT + lane];
        if (f == 1)      e = triples[(token * T_SLOT + lane) * 3 + 1]; // tail
        else if (f == 2) e = triples[(token * T_SLOT + lane) * 3 + 0]; // head
    }
    const unsigned vmask = __ballot_sync(0xffffffffu, e >= 0);
    const int cnt = __popc(vmask & 0xFFFFu);

    const int vrow = inputs[token];   // 4B broadcast load, all lanes same addr

    // ---- entity gather + average: lanes 0..24 own one float4 column group ----
    float4 acc = make_float4(0.f, 0.f, 0.f, 0.f);
    #pragma unroll
    for (int j = 0; j < T_SLOT; ++j) {
        const int ej = __shfl_sync(0xffffffffu, e, j);
        if (ej >= 0 && lane < 25) {
            const float4 r = reinterpret_cast<const float4*>(
                                 ent + (size_t)ej * D_DIM)[lane];
            acc.x += r.x; acc.y += r.y; acc.z += r.z; acc.w += r.w;
        }
    }
    if (lane < 25) {
        const float inv = 1.0f / (float)(cnt > 0 ? cnt : 1);
        acc.x *= inv; acc.y *= inv; acc.z *= inv; acc.w *= inv;
        reinterpret_cast<float4*>(out + (size_t)token * OUT_W + E_DIM)[lane] = acc;
    }

    // ---- token embedding copy: 256 float4 by 32 lanes, 8 iters, coalesced ----
    const float4* __restrict__ src =
        reinterpret_cast<const float4*>(emb + (size_t)vrow * E_DIM);
    float4* __restrict__ dst =
        reinterpret_cast<float4*>(out + (size_t)token * OUT_W);
    #pragma unroll
    for (int i = 0; i < 8; ++i)
        dst[lane + 32 * i] = src[lane + 32 * i];
}

extern "C" void kernel_launch(void* const* d_in, const int* in_sizes, int n_in,
                              void* d_out, int out_size)
{
    const int*   inputs  = (const int*)  d_in[0];
    const int*   triples = (const int*)  d_in[1];
    const int*   flags   = (const int*)  d_in[2];
    const float* emb     = (const float*)d_in[3];
    const float* ent     = (const float*)d_in[4];
    float*       out     = (float*)      d_out;

    // one warp per token: 8192 warps = 1024 blocks * 8 warps
    fuse_triples_warp_kernel<<<NTOK / 8, 256>>>(inputs, triples, flags, emb, ent, out);
}